// round 9
// baseline (speedup 1.0000x reference)
#include <cuda_runtime.h>
#include <cuda_fp16.h>
#include <stdint.h>
#include <string.h>

// Problem constants
#define IN_F   2048
#define OUTF   512
#define NB     8
#define BATCH  16

// Packed bits: g_pkw[fb16][out*4+sub] : uint32. Bit pair (2j, 2j+1) holds the
// binarized weights for f = fb16*16 + j, columns out*8 + 2*sub + {0,1}.
// Independent of batch. Dims: 128 x 2048 = 262144 words = 1 MB.
__device__ uint32_t g_pkw[128 * 2048];

static __device__ __forceinline__ __half2 u2h2(uint32_t u) {
    __half2 h; memcpy(&h, &u, 4); return h;
}
static __device__ __forceinline__ uint32_t h22u(__half2 h) {
    uint32_t u; memcpy(&u, &h, 4); return u;
}

// ---------------------------------------------------------------------------
// Pack kernel: binarize weight (>= 0.5), 2 bits per f (adjacent columns),
// 16 f per word. idx = fb16*2048 + (out*4 + sub); columns rem*2, rem*2+1.
// ---------------------------------------------------------------------------
__global__ void pack_kernel(const float* __restrict__ w) {
    int idx = blockIdx.x * blockDim.x + threadIdx.x;
    int fb16 = idx >> 11;         // f-chunk of 16
    int rem  = idx & 2047;        // out*4 + sub -> column base = rem*2
    const float2* wp = reinterpret_cast<const float2*>(w) + rem;
    uint32_t word = 0;
#pragma unroll
    for (int j = 0; j < 16; j++) {
        float2 v = __ldg(wp + (size_t)(fb16 * 16 + j) * 2048);
        word |= ((v.x >= 0.5f ? 1u : 0u) | (v.y >= 0.5f ? 2u : 0u)) << (2 * j);
    }
    g_pkw[idx] = word;
}

// ---------------------------------------------------------------------------
// Scan kernel. Thread sub in {0..3} owns lanes {2sub, 2sub+1} of row-pair
// (b0, b0+8): half2 state A = lane 2sub, B = lane 2sub+1 (each packs the two
// batch rows). LOW-LATENCY CSA step (6 fp16 fma ops, re-associated):
//   ga = fma(a,-2,1)          (dep a only)
//   r  = fma(s, ga, a)        (s -> r : 4 cyc)          r  = xor(s,a)
//   m1 = s*a
//   mj = fma(c, r, m1)                                  mj = maj(s,a,c)
//   gc = fma(c,-2,1)          (dep c only, arrives early)
//   s' = fma(r, gc, c)        (r -> s' : 4 cyc)         s' = xor(r,c)
// s-recurrence = 8 cyc/step (was 16). SKEWED PIPELINE as R8: iteration i runs
// A-step(f=i-1) then B-step(f=i); cB(i)=mjA(i) same-iteration register;
// cA(i-1)=neighbor mjB(i-2) via a shfl issued 2 iterations earlier.
// Both chains start from (s=0,c=0): a (0,0)-step yields exactly (s=a, c=0).
// Grid: 128 blocks x 128 threads = 512 warps = 1 warp/SMSP on 128 SMs.
// ---------------------------------------------------------------------------
__global__ void __launch_bounds__(128, 1)
scan_kernel(const float* __restrict__ x, float* __restrict__ out) {
    __shared__ uint32_t sx[IN_F];   // {half(x[b0,f]), half(x[b0+8,f])}

    const int tid = threadIdx.x;
    const int blk = blockIdx.x;
    const int b0 = blk >> 4;                 // 0..7 ; pair row is b0+8
    const int out_base = (blk & 15) << 5;    // 32 outs per block

    const float* xa = x + b0 * IN_F;
    const float* xb = x + (b0 + 8) * IN_F;
#pragma unroll
    for (int i = 0; i < IN_F / 128; i++) {
        int k = tid + i * 128;
        sx[k] = h22u(__halves2half2(__float2half(xa[k]), __float2half(xb[k])));
    }
    __syncthreads();

    const int sub  = tid & 3;
    const int lane = tid & 31;
    const int srcl = sub ? (lane - 1) : lane;       // carry source lane
    const uint32_t zmask = sub ? 0xFFFFFFFFu : 0u;  // lane-0 carry-in is 0
    const uint32_t* pk = g_pkw + out_base * 4 + tid;   // + fb16*2048 per chunk
    const __half2 neg2 = __float2half2_rn(-2.0f);
    const __half2 one  = __float2half2_rn(1.0f);
    const __half2 zero = __float2half2_rn(0.0f);

    // sign-extend bit `b` of v to a full mask
    auto sext = [](uint32_t v, int b) {
        return (uint32_t)(((int32_t)(v << (31 - b))) >> 31);
    };

    __half2 sA = zero, sB = zero;
    uint32_t p1 = 0, p2 = 0;            // shfl pipeline: p2 is 2 iters old

    // One pipelined iteration: A-step(f-1) then B-step(f).
    auto stepAB = [&](uint32_t mAu, uint32_t xuA, uint32_t mBu, uint32_t xuB) {
        // ---- A-step (f = i-1); cA = 2-iteration-old neighbor mjB ----
        __half2 cAv = u2h2(p2 & zmask);
        __half2 aA  = u2h2(xuA & mAu);
        __half2 gcA = __hfma2(cAv, neg2, one);   // dep c only (early)
        __half2 gaA = __hfma2(aA, neg2, one);    // dep a only
        __half2 rA  = __hfma2(sA, gaA, aA);      // s -> r
        __half2 m1A = __hmul2(sA, aA);
        __half2 mjA = __hfma2(cAv, rA, m1A);     // maj
        sA = __hfma2(rA, gcA, cAv);              // r -> s'
        // ---- B-step (f = i); cB = mjA from THIS iteration ----
        __half2 aB  = u2h2(xuB & mBu);
        __half2 gcB = __hfma2(mjA, neg2, one);   // dep cB=mjA
        __half2 gaB = __hfma2(aB, neg2, one);
        __half2 rB  = __hfma2(sB, gaB, aB);
        __half2 m1B = __hmul2(sB, aB);
        __half2 mjB = __hfma2(mjA, rB, m1B);
        sB = __hfma2(rB, gcB, mjA);
        // ---- carry exchange, consumed 2 iterations later ----
        p2 = p1;
        p1 = __shfl_sync(0xFFFFFFFFu, h22u(mjB), srcl);
    };

    const uint4* sx4 = reinterpret_cast<const uint4*>(sx);

    uint32_t w = __ldg(pk);
    uint32_t wprev = 0;                 // bits for f<0 read as 0 (identity)
    uint32_t xu_lag = 0;

#pragma unroll 1
    for (int fb16 = 0; fb16 < 128; fb16++) {
        uint32_t wnext = 0;
        if (fb16 < 127) wnext = __ldg(pk + (fb16 + 1) * 2048);
        const uint4* p = sx4 + fb16 * 4;
        uint4 q0 = p[0], q1 = p[1], q2 = p[2], q3 = p[3];
        stepAB(sext(wprev, 30), xu_lag, sext(w, 1),  q0.x);
        stepAB(sext(w, 0),  q0.x, sext(w, 3),  q0.y);
        stepAB(sext(w, 2),  q0.y, sext(w, 5),  q0.z);
        stepAB(sext(w, 4),  q0.z, sext(w, 7),  q0.w);
        stepAB(sext(w, 6),  q0.w, sext(w, 9),  q1.x);
        stepAB(sext(w, 8),  q1.x, sext(w, 11), q1.y);
        stepAB(sext(w, 10), q1.y, sext(w, 13), q1.z);
        stepAB(sext(w, 12), q1.z, sext(w, 15), q1.w);
        stepAB(sext(w, 14), q1.w, sext(w, 17), q2.x);
        stepAB(sext(w, 16), q2.x, sext(w, 19), q2.y);
        stepAB(sext(w, 18), q2.y, sext(w, 21), q2.z);
        stepAB(sext(w, 20), q2.z, sext(w, 23), q2.w);
        stepAB(sext(w, 22), q2.w, sext(w, 25), q3.x);
        stepAB(sext(w, 24), q3.x, sext(w, 27), q3.y);
        stepAB(sext(w, 26), q3.y, sext(w, 29), q3.z);
        stepAB(sext(w, 28), q3.z, sext(w, 31), q3.w);
        xu_lag = q3.w;
        wprev = w;
        w = wnext;
    }

    // Drain: final A-step (f = 2047). cA = p2 = shfl(mjB(2046)).
    __half2 cB_fin, cA_fin;
    {
        __half2 cAv = u2h2(p2 & zmask);
        __half2 aA  = u2h2(xu_lag & sext(wprev, 30));
        __half2 gcA = __hfma2(cAv, neg2, one);
        __half2 gaA = __hfma2(aA, neg2, one);
        __half2 rA  = __hfma2(sA, gaA, aA);
        __half2 m1A = __hmul2(sA, aA);
        __half2 mjA = __hfma2(cAv, rA, m1A);
        sA = __hfma2(rA, gcA, cAv);
        cB_fin = mjA;                        // carry into lane 2sub+1
        cA_fin = u2h2(p1 & zmask);           // shfl(mjB(2047)) from last iter
    }

    // Output float32. Thread sub holds lanes (2sub, 2sub+1) of rows b0, b0+8.
    // s at out[b*4096 + o*8 + lane], c at +65536 floats.
    const int out_i = out_base + (tid >> 2);
    const int baseA = b0 * 4096 + out_i * 8 + 2 * sub;        // row b0
    const int baseB = baseA + 8 * 4096;                       // row b0+8
    float2 sAf = __half22float2(sA), cAf = __half22float2(cA_fin);
    float2 sBf = __half22float2(sB), cBf = __half22float2(cB_fin);
    out[baseA]             = sAf.x;   // row b0,   lane 2sub
    out[baseA + 1]         = sBf.x;   // row b0,   lane 2sub+1
    out[baseB]             = sAf.y;   // row b0+8, lane 2sub
    out[baseB + 1]         = sBf.y;
    out[65536 + baseA]     = cAf.x;
    out[65536 + baseA + 1] = cBf.x;
    out[65536 + baseB]     = cAf.y;
    out[65536 + baseB + 1] = cBf.y;
}

// ---------------------------------------------------------------------------
extern "C" void kernel_launch(void* const* d_in, const int* in_sizes, int n_in,
                              void* d_out, int out_size) {
    const float* x  = (const float*)d_in[0];   // (16, 2048) fp32
    const float* wt = (const float*)d_in[1];   // (2048, 4096) fp32
    float* out = (float*)d_out;                // 131072 fp32: [s | c]

    pack_kernel<<<1024, 256>>>(wt);
    scan_kernel<<<128, 128>>>(x, out);
}

// round 10
// speedup vs baseline: 1.0149x; 1.0149x over previous
#include <cuda_runtime.h>
#include <cuda_fp16.h>
#include <stdint.h>
#include <string.h>

// Problem constants
#define IN_F   2048
#define OUTF   512
#define NB     8
#define BATCH  16

// Packed bits: g_pkw[fb16][out*4+sub] : uint32. Bit pair (2j, 2j+1) holds the
// binarized weights for f = fb16*16 + j, columns out*8 + 2*sub + {0,1}.
// Independent of batch. Dims: 128 x 2048 = 262144 words = 1 MB.
__device__ uint32_t g_pkw[128 * 2048];

static __device__ __forceinline__ __half2 u2h2(uint32_t u) {
    __half2 h; memcpy(&h, &u, 4); return h;
}
static __device__ __forceinline__ uint32_t h22u(__half2 h) {
    uint32_t u; memcpy(&u, &h, 4); return u;
}

#define ONEU 0x3C003C00u   // half2 {1.0, 1.0}

// ---------------------------------------------------------------------------
// Pack kernel: binarize weight (>= 0.5), 2 bits per f (adjacent columns),
// 16 f per word. idx = fb16*2048 + (out*4 + sub); columns rem*2, rem*2+1.
// ---------------------------------------------------------------------------
__global__ void pack_kernel(const float* __restrict__ w) {
    int idx = blockIdx.x * blockDim.x + threadIdx.x;
    int fb16 = idx >> 11;         // f-chunk of 16
    int rem  = idx & 2047;        // out*4 + sub -> column base = rem*2
    const float2* wp = reinterpret_cast<const float2*>(w) + rem;
    uint32_t word = 0;
#pragma unroll
    for (int j = 0; j < 16; j++) {
        float2 v = __ldg(wp + (size_t)(fb16 * 16 + j) * 2048);
        word |= ((v.x >= 0.5f ? 1u : 0u) | (v.y >= 0.5f ? 2u : 0u)) << (2 * j);
    }
    g_pkw[idx] = word;
}

// ---------------------------------------------------------------------------
// Scan kernel. Thread sub in {0..3} owns lanes {2sub, 2sub+1} of row-pair
// (b0, b0+8): half2 state A = lane 2sub, B = lane 2sub+1 (each packs the two
// batch rows). CSA step per half2 -- 5 fma + 2 LOP3, bit-exact vs R9:
//   a  = xu & m                           (LOP)
//   ga = (gax & m) | (ONE & ~m)           (LOP3; == fma(a,-2,1) exactly,
//                                          gax = fma(x,-2,1) precomputed)
//   r  = fma(s, ga, a)                    r  = xor(s,a)
//   m1 = s*a
//   mj = fma(c, r, m1)                    mj = maj(s,a,c)
//   gc = fma(c,-2,1)
//   s' = fma(r, gc, c)                    s' = xor(r,c)
// SKEWED PIPELINE (as R8/R9): iteration i runs A-step(f=i-1) then B-step(f=i);
// cB(i)=mjA(i) same-iteration register; cA(i-1)=neighbor mjB(i-2) via a shfl
// issued 2 iterations earlier. Masks come from a 4-entry LUT (LDS.64); the
// A-mask/x/gax for f=i are carried to iteration i+1 by register rotation.
// Grid: 128 blocks x 128 threads = 512 warps = 1 warp/SMSP on 128 SMs.
// ---------------------------------------------------------------------------
__global__ void __launch_bounds__(128, 1)
scan_kernel(const float* __restrict__ x, float* __restrict__ out) {
    __shared__ uint32_t su[2 * IN_F];   // su[2f] = {x[b0,f],x[b0+8,f]} as half2
                                        // su[2f+1] = fma(that, -2, 1)
    __shared__ uint2 slut4[4];          // 2-bit pattern -> (maskA, maskB)

    const int tid = threadIdx.x;
    const int blk = blockIdx.x;
    const int b0 = blk >> 4;                 // 0..7 ; pair row is b0+8
    const int out_base = (blk & 15) << 5;    // 32 outs per block

    const float* xa = x + b0 * IN_F;
    const float* xb = x + (b0 + 8) * IN_F;
    const __half2 neg2 = __float2half2_rn(-2.0f);
    const __half2 one  = __float2half2_rn(1.0f);
    const __half2 zero = __float2half2_rn(0.0f);
#pragma unroll
    for (int i = 0; i < IN_F / 128; i++) {
        int k = tid + i * 128;
        __half2 pr = __halves2half2(__float2half(xa[k]), __float2half(xb[k]));
        __half2 gx = __hfma2(pr, neg2, one);      // same op as old in-loop ga
        reinterpret_cast<uint2*>(su)[k] = make_uint2(h22u(pr), h22u(gx));
    }
    if (tid < 4)
        slut4[tid] = make_uint2((tid & 1) ? 0xFFFFFFFFu : 0u,
                                (tid & 2) ? 0xFFFFFFFFu : 0u);
    __syncthreads();

    const int sub  = tid & 3;
    const int lane = tid & 31;
    const int srcl = sub ? (lane - 1) : lane;       // carry source lane
    const uint32_t zmask = sub ? 0xFFFFFFFFu : 0u;  // lane-0 carry-in is 0
    const uint32_t* pk = g_pkw + out_base * 4 + tid;   // + fb16*2048 per chunk

    __half2 sA = zero, sB = zero;
    uint32_t p1 = 0, p2 = 0;              // shfl pipeline: p2 is 2 iters old
    uint32_t mA_lag = 0, xu_lag = 0, gax_lag = 0;   // f = -1: a = 0 identity

    // One pipelined iteration: A-step(f-1) then B-step(f).
    auto stepAB = [&](uint32_t mB, uint32_t xu, uint32_t gax, uint32_t mA_cur) {
        // ---- A-step (f = i-1); cA = 2-iteration-old neighbor mjB ----
        __half2 cAv = u2h2(p2 & zmask);
        __half2 aA  = u2h2(xu_lag & mA_lag);
        __half2 gaA = u2h2((gax_lag & mA_lag) | (ONEU & ~mA_lag));
        __half2 rA  = __hfma2(sA, gaA, aA);
        __half2 m1A = __hmul2(sA, aA);
        __half2 mjA = __hfma2(cAv, rA, m1A);
        __half2 gcA = __hfma2(cAv, neg2, one);
        sA = __hfma2(rA, gcA, cAv);
        // ---- B-step (f = i); cB = mjA from THIS iteration ----
        __half2 aB  = u2h2(xu & mB);
        __half2 gaB = u2h2((gax & mB) | (ONEU & ~mB));
        __half2 rB  = __hfma2(sB, gaB, aB);
        __half2 m1B = __hmul2(sB, aB);
        __half2 mjB = __hfma2(mjA, rB, m1B);
        __half2 gcB = __hfma2(mjA, neg2, one);
        sB = __hfma2(rB, gcB, mjA);
        // ---- carry exchange, consumed 2 iterations later ----
        p2 = p1;
        p1 = __shfl_sync(0xFFFFFFFFu, h22u(mjB), srcl);
        // ---- rotate f-state for next iteration's A-step ----
        mA_lag = mA_cur; xu_lag = xu; gax_lag = gax;
    };

    const uint4* su4 = reinterpret_cast<const uint4*>(su);

    uint32_t w = __ldg(pk);

#pragma unroll 1
    for (int fb16 = 0; fb16 < 128; fb16++) {
        uint32_t wnext = 0;
        if (fb16 < 127) wnext = __ldg(pk + (fb16 + 1) * 2048);
        const uint4* p = su4 + fb16 * 8;   // 8 quads = 16 f (xu,gax pairs)
        uint4 u0 = p[0], u1 = p[1], u2 = p[2], u3 = p[3];
        uint4 u4 = p[4], u5 = p[5], u6 = p[6], u7 = p[7];
#pragma unroll
        for (int j = 0; j < 16; j++) {
            uint2 mm = slut4[(w >> (2 * j)) & 3u];
            uint32_t xu, gax;
            switch (j >> 1) {
                case 0: xu = (j & 1) ? u0.z : u0.x; gax = (j & 1) ? u0.w : u0.y; break;
                case 1: xu = (j & 1) ? u1.z : u1.x; gax = (j & 1) ? u1.w : u1.y; break;
                case 2: xu = (j & 1) ? u2.z : u2.x; gax = (j & 1) ? u2.w : u2.y; break;
                case 3: xu = (j & 1) ? u3.z : u3.x; gax = (j & 1) ? u3.w : u3.y; break;
                case 4: xu = (j & 1) ? u4.z : u4.x; gax = (j & 1) ? u4.w : u4.y; break;
                case 5: xu = (j & 1) ? u5.z : u5.x; gax = (j & 1) ? u5.w : u5.y; break;
                case 6: xu = (j & 1) ? u6.z : u6.x; gax = (j & 1) ? u6.w : u6.y; break;
                default: xu = (j & 1) ? u7.z : u7.x; gax = (j & 1) ? u7.w : u7.y; break;
            }
            stepAB(mm.y, xu, gax, mm.x);
        }
        w = wnext;
    }

    // Drain: final A-step (f = 2047). cA = p2 = shfl(mjB(2046)).
    __half2 cB_fin, cA_fin;
    {
        __half2 cAv = u2h2(p2 & zmask);
        __half2 aA  = u2h2(xu_lag & mA_lag);
        __half2 gaA = u2h2((gax_lag & mA_lag) | (ONEU & ~mA_lag));
        __half2 rA  = __hfma2(sA, gaA, aA);
        __half2 m1A = __hmul2(sA, aA);
        __half2 mjA = __hfma2(cAv, rA, m1A);
        __half2 gcA = __hfma2(cAv, neg2, one);
        sA = __hfma2(rA, gcA, cAv);
        cB_fin = mjA;                        // carry into lane 2sub+1
        cA_fin = u2h2(p1 & zmask);           // shfl(mjB(2047)) from last iter
    }

    // Output float32. Thread sub holds lanes (2sub, 2sub+1) of rows b0, b0+8.
    // s at out[b*4096 + o*8 + lane], c at +65536 floats.
    const int out_i = out_base + (tid >> 2);
    const int baseA = b0 * 4096 + out_i * 8 + 2 * sub;        // row b0
    const int baseB = baseA + 8 * 4096;                       // row b0+8
    float2 sAf = __half22float2(sA), cAf = __half22float2(cA_fin);
    float2 sBf = __half22float2(sB), cBf = __half22float2(cB_fin);
    out[baseA]             = sAf.x;   // row b0,   lane 2sub
    out[baseA + 1]         = sBf.x;   // row b0,   lane 2sub+1
    out[baseB]             = sAf.y;   // row b0+8, lane 2sub
    out[baseB + 1]         = sBf.y;
    out[65536 + baseA]     = cAf.x;
    out[65536 + baseA + 1] = cBf.x;
    out[65536 + baseB]     = cAf.y;
    out[65536 + baseB + 1] = cBf.y;
}

// ---------------------------------------------------------------------------
extern "C" void kernel_launch(void* const* d_in, const int* in_sizes, int n_in,
                              void* d_out, int out_size) {
    const float* x  = (const float*)d_in[0];   // (16, 2048) fp32
    const float* wt = (const float*)d_in[1];   // (2048, 4096) fp32
    float* out = (float*)d_out;                // 131072 fp32: [s | c]

    pack_kernel<<<1024, 256>>>(wt);
    scan_kernel<<<128, 128>>>(x, out);
}